// round 9
// baseline (speedup 1.0000x reference)
#include <cuda_runtime.h>
#include <cuda_bf16.h>
#include <stdint.h>
#include <math.h>

// Problem constants
#define BQ     16
#define QL     30
#define DSEQ   65
#define NTOK   (BQ*QL + BQ*DSEQ)   // 1520
#define NTOKP  1536
#define DMODEL 768
#define NH     8
#define HD     96
#define FFD    3072
#define QKVD   2304

// ---------------- scratch ----------------
__device__ float g_X   [NTOKP * DMODEL];
__device__ float g_X0q [BQ * DMODEL];
__device__ float g_QKV [NTOKP * QKVD];
__device__ float g_ATT [NTOKP * DMODEL];
__device__ float g_TMP [NTOKP * DMODEL];
__device__ float g_H   [NTOKP * FFD];
__device__ float g_PV  [32 * DMODEL];
__device__ uint2 g_WqkvSP[2 * DMODEL * QKVD];
__device__ uint2 g_WoSP  [2 * DMODEL * DMODEL];
__device__ uint2 g_W1SP  [2 * DMODEL * FFD];
__device__ uint2 g_W2SP  [2 * FFD * DMODEL];
__device__ uint2 g_ACT   [NTOKP * FFD];

// ---------------- helpers ----------------
__device__ __forceinline__ void cp16(void* smem, const void* g) {
    uint32_t s = (uint32_t)__cvta_generic_to_shared(smem);
    asm volatile("cp.async.ca.shared.global [%0], [%1], 16;" :: "r"(s), "l"(g));
}
__device__ __forceinline__ void f32split(float x, uint32_t& hi, uint32_t& lo) {
    uint32_t h, l;
    asm("cvt.rna.tf32.f32 %0, %1;" : "=r"(h) : "f"(x));
    float hf = __uint_as_float(h);
    asm("cvt.rna.tf32.f32 %0, %1;" : "=r"(l) : "f"(x - hf));
    hi = h; lo = l;
}
__device__ __forceinline__ void mma8(float* c, const uint32_t* a, const uint32_t* b) {
    asm volatile("mma.sync.aligned.m16n8k8.row.col.f32.tf32.tf32.f32 "
                 "{%0,%1,%2,%3}, {%4,%5,%6,%7}, {%8,%9}, {%0,%1,%2,%3};"
                 : "+f"(c[0]), "+f"(c[1]), "+f"(c[2]), "+f"(c[3])
                 : "r"(a[0]), "r"(a[1]), "r"(a[2]), "r"(a[3]),
                   "r"(b[0]), "r"(b[1]));
}
__device__ __forceinline__ float gelu_f(float x) {
    return 0.5f * x * (1.f + tanhf(0.7978845608028654f * (x + 0.044715f * x * x * x)));
}

// ---------------- split: f32 -> (tf32 hi, tf32 lo) interleaved ----------------
__global__ void split_kernel(const float* __restrict__ in, uint2* __restrict__ out, int n)
{
    int i = (blockIdx.x * 256 + threadIdx.x) * 4;
    if (i >= n) return;
    float4 v = *reinterpret_cast<const float4*>(in + i);
    uint4 o1, o2;
    f32split(v.x, o1.x, o1.y); f32split(v.y, o1.z, o1.w);
    f32split(v.z, o2.x, o2.y); f32split(v.w, o2.z, o2.w);
    uint4* op = reinterpret_cast<uint4*>(out + i);
    op[0] = o1; op[1] = o2;
}

// ---------------- embedding ----------------
__global__ void embed_kernel(const float* __restrict__ emb,
                             const float* __restrict__ pos_q,
                             const float* __restrict__ pos_d,
                             const float* __restrict__ cls_topic,
                             const int*   __restrict__ query,
                             const int*   __restrict__ document,
                             float* __restrict__ X, float* __restrict__ X0q)
{
    int r = blockIdx.x;
    int tid = threadIdx.x;
    float* xr = X + (size_t)r * DMODEL;
    if (r < BQ * QL) {
        int b = r / QL, t = r % QL;
        const float* e = emb + (size_t)query[b * QL + t] * DMODEL;
        const float* p = pos_q + (size_t)t * DMODEL;
        for (int k = tid; k < DMODEL; k += 256) {
            float v = e[k] + p[k];
            xr[k] = v;
            if (t == 0) X0q[(size_t)b * DMODEL + k] = v;
        }
    } else {
        int rr = r - BQ * QL;
        int b = rr / DSEQ, p = rr % DSEQ;
        if (p == 0) {
            for (int k = tid; k < DMODEL; k += 256) xr[k] = cls_topic[k];
        } else if (p < 8) {
            for (int k = tid; k < DMODEL; k += 256) xr[k] = 0.f;
        } else {
            int t = p - 8;
            const float* e = emb + (size_t)document[b * 2000 + t] * DMODEL;
            const float* pp = pos_d + (size_t)t * DMODEL;
            for (int k = tid; k < DMODEL; k += 256) xr[k] = e[k] + pp[k];
        }
    }
}

// ---------------- tensor-core GEMM: both operands pre-split ----------------
// Tile 128x64x16, 8 warps (4x2), 2 blocks/SM, dynamic smem 58368B.
#define AS(buf,m,k) sm_a[(((buf)<<7) + (m)) * 20 + (k)]
#define BS(buf,k,n) sm_b[(((buf)<<4) + (k)) * 68 + (n)]

template<bool GELU, bool RES>
__global__ void __launch_bounds__(256, 2)
gemm_sp(const uint2* __restrict__ A, const uint2* __restrict__ B,
        const float* __restrict__ bias, const float* __restrict__ Rsd,
        float* __restrict__ C, int M, int N, int K)
{
    extern __shared__ uint2 sm_a[];               // [2][128][20]
    uint2* sm_b = sm_a + 2 * 128 * 20;            // [2][16][68]

    const int tid  = threadIdx.x;
    const int lane = tid & 31, warp = tid >> 5;
    const int wm = warp >> 1, wn = warp & 1;
    const int g  = lane >> 2, tg = lane & 3;
    const int bm = blockIdx.y * 128, bn = blockIdx.x * 64;

    const int ar = tid >> 1, ao = (tid & 1) * 8;   // A: 2 threads/row, 8 u2 each (4x cp16)
    const int br = tid >> 4, bo = (tid & 15) * 2;  // B: 16 threads/k-row

    float acc[2][4][4];
#pragma unroll
    for (int i = 0; i < 2; i++)
#pragma unroll
        for (int j = 0; j < 4; j++)
#pragma unroll
            for (int q = 0; q < 4; q++) acc[i][j][q] = 0.f;

    const int KT = K >> 4;

    {   // prologue
        const uint2* ap = A + (size_t)(bm + ar) * K;
        cp16(&AS(0, ar, ao),     ap + ao);
        cp16(&AS(0, ar, ao + 2), ap + ao + 2);
        cp16(&AS(0, ar, ao + 4), ap + ao + 4);
        cp16(&AS(0, ar, ao + 6), ap + ao + 6);
        const uint2* bp = B + (size_t)br * N + bn;
        cp16(&BS(0, br, bo),      bp + bo);
        cp16(&BS(0, br, bo + 32), bp + bo + 32);
        asm volatile("cp.async.commit_group;");
    }

    for (int kt = 0; kt < KT; kt++) {
        const int buf = kt & 1;
        if (kt + 1 < KT) {
            const int k0 = (kt + 1) << 4;
            const uint2* ap = A + (size_t)(bm + ar) * K + k0;
            cp16(&AS(buf ^ 1, ar, ao),     ap + ao);
            cp16(&AS(buf ^ 1, ar, ao + 2), ap + ao + 2);
            cp16(&AS(buf ^ 1, ar, ao + 4), ap + ao + 4);
            cp16(&AS(buf ^ 1, ar, ao + 6), ap + ao + 6);
            const uint2* bp = B + (size_t)(k0 + br) * N + bn;
            cp16(&BS(buf ^ 1, br, bo),      bp + bo);
            cp16(&BS(buf ^ 1, br, bo + 32), bp + bo + 32);
            asm volatile("cp.async.commit_group;");
            asm volatile("cp.async.wait_group 1;");
        } else {
            asm volatile("cp.async.wait_group 0;");
        }
        __syncthreads();

#pragma unroll
        for (int ks = 0; ks < 2; ks++) {
            const int k8 = ks * 8;
            uint32_t ahi[2][4], alo[2][4];
#pragma unroll
            for (int mf = 0; mf < 2; mf++) {
                const int mb = wm * 32 + mf * 16;
                uint2 a0 = AS(buf, mb + g,     k8 + tg);
                uint2 a1 = AS(buf, mb + g + 8, k8 + tg);
                uint2 a2 = AS(buf, mb + g,     k8 + tg + 4);
                uint2 a3 = AS(buf, mb + g + 8, k8 + tg + 4);
                ahi[mf][0] = a0.x; alo[mf][0] = a0.y;
                ahi[mf][1] = a1.x; alo[mf][1] = a1.y;
                ahi[mf][2] = a2.x; alo[mf][2] = a2.y;
                ahi[mf][3] = a3.x; alo[mf][3] = a3.y;
            }
#pragma unroll
            for (int nf = 0; nf < 4; nf++) {
                const int nb = wn * 32 + nf * 8 + g;
                uint2 b0 = BS(buf, k8 + tg,     nb);
                uint2 b1 = BS(buf, k8 + tg + 4, nb);
                uint32_t bh[2] = {b0.x, b1.x};
                uint32_t bl[2] = {b0.y, b1.y};
#pragma unroll
                for (int mf = 0; mf < 2; mf++) {
                    mma8(acc[mf][nf], ahi[mf], bh);
                    mma8(acc[mf][nf], ahi[mf], bl);
                    mma8(acc[mf][nf], alo[mf], bh);
                }
            }
        }
        __syncthreads();
    }

    // epilogue
#pragma unroll
    for (int mf = 0; mf < 2; mf++) {
#pragma unroll
        for (int nf = 0; nf < 4; nf++) {
            const int c0 = bn + wn * 32 + nf * 8 + 2 * tg;
#pragma unroll
            for (int half = 0; half < 2; half++) {
                const int r = bm + wm * 32 + mf * 16 + g + half * 8;
                if (r < M) {
                    float v0 = acc[mf][nf][half * 2 + 0] + bias[c0];
                    float v1 = acc[mf][nf][half * 2 + 1] + bias[c0 + 1];
                    if (RES) { v0 += Rsd[(size_t)r * N + c0]; v1 += Rsd[(size_t)r * N + c0 + 1]; }
                    if (GELU) { v0 = gelu_f(v0); v1 = gelu_f(v1); }
                    *reinterpret_cast<float2*>(&C[(size_t)r * N + c0]) = make_float2(v0, v1);
                }
            }
        }
    }
}

// ---------------- attention ----------------
__global__ void attn_kernel(const float* __restrict__ QKV, float* __restrict__ ATT)
{
    __shared__ float Ks[65 * 97];
    __shared__ float Qs[4][96];
    __shared__ float Pw[4][68];
    int s = blockIdx.x;
    int h = blockIdx.y;
    int tid = threadIdx.x;
    int warp = tid >> 5, lane = tid & 31;

    int start, len;
    if (s < BQ) { start = QL * s; len = QL; }
    else        { start = BQ * QL + DSEQ * (s - BQ); len = DSEQ; }

    for (int idx = tid; idx < len * HD; idx += 128) {
        int r = idx / HD, c = idx % HD;
        Ks[r * 97 + c] = QKV[(size_t)(start + r) * QKVD + DMODEL + h * HD + c];
    }
    __syncthreads();

    const float scale = 0.10206207261596575f;

    for (int qi = warp; qi < len; qi += 4) {
        for (int c = lane; c < HD; c += 32)
            Qs[warp][c] = QKV[(size_t)(start + qi) * QKVD + h * HD + c];
        __syncwarp();

        float sj[3];
        float mx = -1e30f;
#pragma unroll
        for (int u = 0; u < 3; u++) {
            int j = lane + 32 * u;
            float d = 0.f;
            if (j < len) {
                const float* kr = &Ks[j * 97];
#pragma unroll
                for (int c = 0; c < HD; c++) d = fmaf(Qs[warp][c], kr[c], d);
                d *= scale;
                mx = fmaxf(mx, d);
            }
            sj[u] = d;
        }
        for (int o = 16; o > 0; o >>= 1) mx = fmaxf(mx, __shfl_xor_sync(0xffffffffu, mx, o));
        float sum = 0.f;
#pragma unroll
        for (int u = 0; u < 3; u++) {
            int j = lane + 32 * u;
            float p = 0.f;
            if (j < len) p = expf(sj[u] - mx);
            sj[u] = p; sum += p;
        }
        for (int o = 16; o > 0; o >>= 1) sum += __shfl_xor_sync(0xffffffffu, sum, o);
        float inv = 1.f / sum;
#pragma unroll
        for (int u = 0; u < 3; u++) {
            int j = lane + 32 * u;
            if (j < len) Pw[warp][j] = sj[u] * inv;
        }
        __syncwarp();

#pragma unroll
        for (int u = 0; u < 3; u++) {
            int dcol = lane + 32 * u;
            float acc = 0.f;
            for (int j = 0; j < len; j++)
                acc = fmaf(Pw[warp][j],
                           QKV[(size_t)(start + j) * QKVD + 2 * DMODEL + h * HD + dcol], acc);
            ATT[(size_t)(start + qi) * DMODEL + h * HD + dcol] = acc;
        }
        __syncwarp();
    }
}

// ---------------- layernorm ----------------
__global__ void ln_kernel(const float* __restrict__ in, const float* __restrict__ g,
                          const float* __restrict__ b, float* __restrict__ out)
{
    __shared__ float red[16];
    int r = blockIdx.x, tid = threadIdx.x;
    const float* x = in + (size_t)r * DMODEL;
    float v0 = x[tid], v1 = x[tid + 256], v2 = x[tid + 512];
    float s = v0 + v1 + v2;
    float ss = v0 * v0 + v1 * v1 + v2 * v2;
    for (int o = 16; o > 0; o >>= 1) {
        s  += __shfl_xor_sync(0xffffffffu, s, o);
        ss += __shfl_xor_sync(0xffffffffu, ss, o);
    }
    int warp = tid >> 5, lane = tid & 31;
    if (lane == 0) { red[warp] = s; red[warp + 8] = ss; }
    __syncthreads();
    if (tid < 32) {
        float a = (tid < 8) ? red[tid] : 0.f;
        float c = (tid < 8) ? red[tid + 8] : 0.f;
        for (int o = 4; o > 0; o >>= 1) {
            a += __shfl_xor_sync(0xffffffffu, a, o);
            c += __shfl_xor_sync(0xffffffffu, c, o);
        }
        if (tid == 0) { red[0] = a; red[1] = c; }
    }
    __syncthreads();
    float mean = red[0] * (1.f / DMODEL);
    float var  = red[1] * (1.f / DMODEL) - mean * mean;
    float inv  = rsqrtf(var + 1e-5f);
    float* o = out + (size_t)r * DMODEL;
    o[tid]       = (v0 - mean) * inv * g[tid]       + b[tid];
    o[tid + 256] = (v1 - mean) * inv * g[tid + 256] + b[tid + 256];
    o[tid + 512] = (v2 - mean) * inv * g[tid + 512] + b[tid + 512];
}

// ---------------- pooler ----------------
__global__ void pool_kernel(const float* __restrict__ X, const float* __restrict__ X0q,
                            const float* __restrict__ cls_topic,
                            const float* __restrict__ W, const float* __restrict__ bias,
                            const float* __restrict__ mixer, float* __restrict__ PV)
{
    int i = blockIdx.x, tid = threadIdx.x;
    __shared__ float xin[DMODEL];
    float mx = mixer[0];
    for (int k = tid; k < DMODEL; k += 256) {
        float pre, post;
        if (i < BQ) {
            pre  = X0q[(size_t)i * DMODEL + k];
            post = X[(size_t)(QL * i) * DMODEL + k];
        } else {
            pre  = cls_topic[k];
            post = X[(size_t)(BQ * QL + DSEQ * (i - BQ)) * DMODEL + k];
        }
        xin[k] = mx * pre + (1.f - mx) * post;
    }
    __syncthreads();
    for (int n = tid; n < DMODEL; n += 256) {
        const float* w = W + (size_t)n * DMODEL;
        float acc = bias[n];
        for (int k = 0; k < DMODEL; k++) acc = fmaf(xin[k], w[k], acc);
        PV[(size_t)i * DMODEL + n] = acc;
    }
}

// ---------------- normalize & scatter ----------------
__global__ void norm_kernel(const float* __restrict__ PV, float* __restrict__ out)
{
    __shared__ float red[8];
    int i = blockIdx.x, tid = threadIdx.x;
    const float* x = PV + (size_t)i * DMODEL;
    float ss = 0.f;
    for (int k = tid; k < DMODEL; k += 256) { float v = x[k]; ss += v * v; }
    for (int o = 16; o > 0; o >>= 1) ss += __shfl_xor_sync(0xffffffffu, ss, o);
    int warp = tid >> 5, lane = tid & 31;
    if (lane == 0) red[warp] = ss;
    __syncthreads();
    if (tid < 32) {
        float a = (tid < 8) ? red[tid] : 0.f;
        for (int o = 4; o > 0; o >>= 1) a += __shfl_xor_sync(0xffffffffu, a, o);
        if (tid == 0) red[0] = a;
    }
    __syncthreads();
    float inv = 1.f / (sqrtf(red[0]) + 1e-4f);
    float* dst = out + 16 + ((i < BQ) ? (size_t)i * DMODEL
                                      : (size_t)BQ * DMODEL + (size_t)(i - BQ) * DMODEL);
    for (int k = tid; k < DMODEL; k += 256) dst[k] = x[k] * inv;
}

__global__ void score_kernel(float* __restrict__ out)
{
    __shared__ float red[8];
    int b = blockIdx.x, tid = threadIdx.x;
    const float* q = out + 16 + (size_t)b * DMODEL;
    const float* d = out + 16 + (size_t)BQ * DMODEL + (size_t)b * DMODEL;
    float s = 0.f;
    for (int k = tid; k < DMODEL; k += 256) s = fmaf(q[k], d[k], s);
    for (int o = 16; o > 0; o >>= 1) s += __shfl_xor_sync(0xffffffffu, s, o);
    int warp = tid >> 5, lane = tid & 31;
    if (lane == 0) red[warp] = s;
    __syncthreads();
    if (tid == 0) {
        float t = 0.f;
        for (int w = 0; w < 8; w++) t += red[w];
        out[b] = 6.f * t;
    }
}

// ---------------- launch ----------------
#define GEMM_SMEM 58368

extern "C" void kernel_launch(void* const* d_in, const int* in_sizes, int n_in,
                              void* d_out, int out_size)
{
    const float* emb       = (const float*)d_in[0];
    const float* pos_q     = (const float*)d_in[1];
    const float* pos_d     = (const float*)d_in[2];
    const float* cls_topic = (const float*)d_in[3];
    const float* mixer     = (const float*)d_in[4];
    const float* pw        = (const float*)d_in[5];
    const float* pb        = (const float*)d_in[6];
    const float* Wqkv      = (const float*)d_in[7];
    const float* bqkv      = (const float*)d_in[8];
    const float* Wo        = (const float*)d_in[9];
    const float* bo        = (const float*)d_in[10];
    const float* g1        = (const float*)d_in[11];
    const float* b1        = (const float*)d_in[12];
    const float* W1        = (const float*)d_in[13];
    const float* bf1       = (const float*)d_in[14];
    const float* W2        = (const float*)d_in[15];
    const float* bf2       = (const float*)d_in[16];
    const float* g2        = (const float*)d_in[17];
    const float* b2        = (const float*)d_in[18];
    const int*   query     = (const int*)d_in[19];
    const int*   document  = (const int*)d_in[20];
    float* out = (float*)d_out;

    float *X, *X0, *QKV, *ATT, *TMP, *Hb, *PV;
    uint2 *WqkvSP, *WoSP, *W1SP, *W2SP, *ACT;
    cudaGetSymbolAddress((void**)&X,   g_X);
    cudaGetSymbolAddress((void**)&X0,  g_X0q);
    cudaGetSymbolAddress((void**)&QKV, g_QKV);
    cudaGetSymbolAddress((void**)&ATT, g_ATT);
    cudaGetSymbolAddress((void**)&TMP, g_TMP);
    cudaGetSymbolAddress((void**)&Hb,  g_H);
    cudaGetSymbolAddress((void**)&PV,  g_PV);
    cudaGetSymbolAddress((void**)&WqkvSP, g_WqkvSP);
    cudaGetSymbolAddress((void**)&WoSP,   g_WoSP);
    cudaGetSymbolAddress((void**)&W1SP,   g_W1SP);
    cudaGetSymbolAddress((void**)&W2SP,   g_W2SP);
    cudaGetSymbolAddress((void**)&ACT,    g_ACT);

    // raise dynamic smem limit (host-side attribute; idempotent)
    cudaFuncSetAttribute(gemm_sp<false, false>, cudaFuncAttributeMaxDynamicSharedMemorySize, GEMM_SMEM);
    cudaFuncSetAttribute(gemm_sp<false, true>,  cudaFuncAttributeMaxDynamicSharedMemorySize, GEMM_SMEM);
    cudaFuncSetAttribute(gemm_sp<true,  false>, cudaFuncAttributeMaxDynamicSharedMemorySize, GEMM_SMEM);

    // weight pre-splits
    split_kernel<<<(2*DMODEL*QKVD)/1024, 256>>>(Wqkv, WqkvSP, 2*DMODEL*QKVD);
    split_kernel<<<(2*DMODEL*DMODEL)/1024, 256>>>(Wo, WoSP, 2*DMODEL*DMODEL);
    split_kernel<<<(2*DMODEL*FFD)/1024, 256>>>(W1, W1SP, 2*DMODEL*FFD);
    split_kernel<<<(2*FFD*DMODEL)/1024, 256>>>(W2, W2SP, 2*FFD*DMODEL);

    embed_kernel<<<NTOK, 256>>>(emb, pos_q, pos_d, cls_topic, query, document, X, X0);

    const int MB = NTOKP / 128;   // 12
    for (int l = 0; l < 2; l++) {
        const uint2* wqkv = WqkvSP + (size_t)l * DMODEL * QKVD;
        const uint2* wo   = WoSP   + (size_t)l * DMODEL * DMODEL;
        const uint2* w1   = W1SP   + (size_t)l * DMODEL * FFD;
        const uint2* w2   = W2SP   + (size_t)l * FFD * DMODEL;

        split_kernel<<<(NTOKP*DMODEL)/1024, 256>>>(X, ACT, NTOKP*DMODEL);
        gemm_sp<false, false><<<dim3(QKVD / 64, MB), 256, GEMM_SMEM>>>(
            ACT, wqkv, bqkv + (size_t)l * QKVD, nullptr, QKV, NTOK, QKVD, DMODEL);

        attn_kernel<<<dim3(32, NH), 128>>>(QKV, ATT);

        split_kernel<<<(NTOKP*DMODEL)/1024, 256>>>(ATT, ACT, NTOKP*DMODEL);
        gemm_sp<false, true><<<dim3(DMODEL / 64, MB), 256, GEMM_SMEM>>>(
            ACT, wo, bo + (size_t)l * DMODEL, X, TMP, NTOK, DMODEL, DMODEL);

        ln_kernel<<<NTOK, 256>>>(TMP, g1 + (size_t)l * DMODEL, b1 + (size_t)l * DMODEL, X);

        split_kernel<<<(NTOKP*DMODEL)/1024, 256>>>(X, ACT, NTOKP*DMODEL);
        gemm_sp<true, false><<<dim3(FFD / 64, MB), 256, GEMM_SMEM>>>(
            ACT, w1, bf1 + (size_t)l * FFD, nullptr, Hb, NTOK, FFD, DMODEL);

        split_kernel<<<(NTOKP*FFD)/1024, 256>>>(Hb, ACT, NTOKP*FFD);
        gemm_sp<false, true><<<dim3(DMODEL / 64, MB), 256, GEMM_SMEM>>>(
            ACT, w2, bf2 + (size_t)l * DMODEL, X, TMP, NTOK, DMODEL, FFD);

        ln_kernel<<<NTOK, 256>>>(TMP, g2 + (size_t)l * DMODEL, b2 + (size_t)l * DMODEL, X);
    }

    pool_kernel<<<32, 256>>>(X, X0, cls_topic, pw, pb, mixer, PV);
    norm_kernel<<<32, 256>>>(PV, out);
    score_kernel<<<16, 256>>>(out);
}

// round 11
// speedup vs baseline: 1.2316x; 1.2316x over previous
#include <cuda_runtime.h>
#include <cuda_bf16.h>
#include <stdint.h>
#include <math.h>

// Problem constants
#define BQ     16
#define QL     30
#define DSEQ   65
#define NTOK   (BQ*QL + BQ*DSEQ)   // 1520
#define NTOKP  1536
#define DMODEL 768
#define NH     8
#define HD     96
#define FFD    3072
#define QKVD   2304

// ---------------- scratch ----------------
__device__ float g_X   [NTOKP * DMODEL];
__device__ float g_X0q [BQ * DMODEL];
__device__ float g_QKV [NTOKP * QKVD];
__device__ float g_ATT [NTOKP * DMODEL];
__device__ float g_TMP [NTOKP * DMODEL];
__device__ float g_H   [NTOKP * FFD];
__device__ float g_PV  [32 * DMODEL];

// ---------------- helpers ----------------
__device__ __forceinline__ void cp16(void* smem, const void* g) {
    uint32_t s = (uint32_t)__cvta_generic_to_shared(smem);
    asm volatile("cp.async.ca.shared.global [%0], [%1], 16;" :: "r"(s), "l"(g));
}
__device__ __forceinline__ void f32split(float x, uint32_t& hi, uint32_t& lo) {
    uint32_t h, l;
    asm("cvt.rna.tf32.f32 %0, %1;" : "=r"(h) : "f"(x));
    float hf = __uint_as_float(h);
    asm("cvt.rna.tf32.f32 %0, %1;" : "=r"(l) : "f"(x - hf));
    hi = h; lo = l;
}
__device__ __forceinline__ void mma8(float* c, const uint32_t* a, const uint32_t* b) {
    asm volatile("mma.sync.aligned.m16n8k8.row.col.f32.tf32.tf32.f32 "
                 "{%0,%1,%2,%3}, {%4,%5,%6,%7}, {%8,%9}, {%0,%1,%2,%3};"
                 : "+f"(c[0]), "+f"(c[1]), "+f"(c[2]), "+f"(c[3])
                 : "r"(a[0]), "r"(a[1]), "r"(a[2]), "r"(a[3]),
                   "r"(b[0]), "r"(b[1]));
}
__device__ __forceinline__ float gelu_f(float x) {
    return 0.5f * x * (1.f + tanhf(0.7978845608028654f * (x + 0.044715f * x * x * x)));
}

// ---------------- embedding ----------------
__global__ void embed_kernel(const float* __restrict__ emb,
                             const float* __restrict__ pos_q,
                             const float* __restrict__ pos_d,
                             const float* __restrict__ cls_topic,
                             const int*   __restrict__ query,
                             const int*   __restrict__ document,
                             float* __restrict__ X, float* __restrict__ X0q)
{
    int r = blockIdx.x;
    int tid = threadIdx.x;
    float* xr = X + (size_t)r * DMODEL;
    if (r < BQ * QL) {
        int b = r / QL, t = r % QL;
        const float* e = emb + (size_t)query[b * QL + t] * DMODEL;
        const float* p = pos_q + (size_t)t * DMODEL;
        for (int k = tid; k < DMODEL; k += 256) {
            float v = e[k] + p[k];
            xr[k] = v;
            if (t == 0) X0q[(size_t)b * DMODEL + k] = v;
        }
    } else {
        int rr = r - BQ * QL;
        int b = rr / DSEQ, p = rr % DSEQ;
        if (p == 0) {
            for (int k = tid; k < DMODEL; k += 256) xr[k] = cls_topic[k];
        } else if (p < 8) {
            for (int k = tid; k < DMODEL; k += 256) xr[k] = 0.f;
        } else {
            int t = p - 8;
            const float* e = emb + (size_t)document[b * 2000 + t] * DMODEL;
            const float* pp = pos_d + (size_t)t * DMODEL;
            for (int k = tid; k < DMODEL; k += 256) xr[k] = e[k] + pp[k];
        }
    }
}

// ---------------- TM=128 tensor-core GEMM (round-6 proven, pass-major mma order) ------
template<bool GELU, bool RES>
__global__ void __launch_bounds__(256)
gemm_tc128(const float* __restrict__ A, const float* __restrict__ B,
           const float* __restrict__ bias, const float* __restrict__ Rsd,
           float* __restrict__ C, int M, int N, int K)
{
    __shared__ float As[2][128][20];
    __shared__ float Bs[2][16][72];

    const int tid  = threadIdx.x;
    const int lane = tid & 31, warp = tid >> 5;
    const int wm = warp >> 1, wn = warp & 1;        // 4 x 2 warps
    const int g  = lane >> 2, tg = lane & 3;
    const int bm = blockIdx.y * 128, bn = blockIdx.x * 64;

    const int am  = tid >> 2;
    const int ak  = (tid & 3) * 4;
    const int bk  = tid >> 4;
    const int bnn = (tid & 15) * 4;

    float acc[2][4][4];
#pragma unroll
    for (int i = 0; i < 2; i++)
#pragma unroll
        for (int j = 0; j < 4; j++)
#pragma unroll
            for (int q = 0; q < 4; q++) acc[i][j][q] = 0.f;

    const int KT = K >> 4;

    {
        const float* ap = A + (size_t)(bm + am) * K + ak;
        cp16(&As[0][am][ak],      ap);
        cp16(&As[0][am + 64][ak], ap + (size_t)64 * K);
        cp16(&Bs[0][bk][bnn],     B + (size_t)bk * N + bn + bnn);
        asm volatile("cp.async.commit_group;");
    }

    for (int kt = 0; kt < KT; kt++) {
        const int buf = kt & 1;
        if (kt + 1 < KT) {
            const int k0 = (kt + 1) << 4;
            const float* ap = A + (size_t)(bm + am) * K + k0 + ak;
            cp16(&As[buf ^ 1][am][ak],      ap);
            cp16(&As[buf ^ 1][am + 64][ak], ap + (size_t)64 * K);
            cp16(&Bs[buf ^ 1][bk][bnn],     B + (size_t)(k0 + bk) * N + bn + bnn);
            asm volatile("cp.async.commit_group;");
            asm volatile("cp.async.wait_group 1;");
        } else {
            asm volatile("cp.async.wait_group 0;");
        }
        __syncthreads();

#pragma unroll
        for (int ks = 0; ks < 2; ks++) {
            const int k8 = ks * 8;
            uint32_t ahi[2][4], alo[2][4];
#pragma unroll
            for (int mf = 0; mf < 2; mf++) {
                const int mb = wm * 32 + mf * 16;
                f32split(As[buf][mb + g    ][k8 + tg    ], ahi[mf][0], alo[mf][0]);
                f32split(As[buf][mb + g + 8][k8 + tg    ], ahi[mf][1], alo[mf][1]);
                f32split(As[buf][mb + g    ][k8 + tg + 4], ahi[mf][2], alo[mf][2]);
                f32split(As[buf][mb + g + 8][k8 + tg + 4], ahi[mf][3], alo[mf][3]);
            }
            uint32_t bhi[4][2], blo[4][2];
#pragma unroll
            for (int nf = 0; nf < 4; nf++) {
                const int nb = wn * 32 + nf * 8;
                f32split(Bs[buf][k8 + tg    ][nb + g], bhi[nf][0], blo[nf][0]);
                f32split(Bs[buf][k8 + tg + 4][nb + g], bhi[nf][1], blo[nf][1]);
            }
            // pass-major: dependents spaced by 8 independent mmas
#pragma unroll
            for (int mf = 0; mf < 2; mf++)
#pragma unroll
                for (int nf = 0; nf < 4; nf++) mma8(acc[mf][nf], ahi[mf], bhi[nf]);
#pragma unroll
            for (int mf = 0; mf < 2; mf++)
#pragma unroll
                for (int nf = 0; nf < 4; nf++) mma8(acc[mf][nf], ahi[mf], blo[nf]);
#pragma unroll
            for (int mf = 0; mf < 2; mf++)
#pragma unroll
                for (int nf = 0; nf < 4; nf++) mma8(acc[mf][nf], alo[mf], bhi[nf]);
        }
        __syncthreads();
    }

#pragma unroll
    for (int mf = 0; mf < 2; mf++) {
#pragma unroll
        for (int nf = 0; nf < 4; nf++) {
            const int c0 = bn + wn * 32 + nf * 8 + 2 * tg;
#pragma unroll
            for (int half = 0; half < 2; half++) {
                const int r = bm + wm * 32 + mf * 16 + g + half * 8;
                if (r < M) {
                    float v0 = acc[mf][nf][half * 2 + 0] + bias[c0];
                    float v1 = acc[mf][nf][half * 2 + 1] + bias[c0 + 1];
                    if (RES) { v0 += Rsd[(size_t)r * N + c0]; v1 += Rsd[(size_t)r * N + c0 + 1]; }
                    if (GELU) { v0 = gelu_f(v0); v1 = gelu_f(v1); }
                    *reinterpret_cast<float2*>(&C[(size_t)r * N + c0]) = make_float2(v0, v1);
                }
            }
        }
    }
}

// ---------------- TM=64 variant (for grid-starved Wo / W2 GEMMs) ----------------
template<bool GELU, bool RES>
__global__ void __launch_bounds__(256)
gemm_tc64(const float* __restrict__ A, const float* __restrict__ B,
          const float* __restrict__ bias, const float* __restrict__ Rsd,
          float* __restrict__ C, int M, int N, int K)
{
    __shared__ float As[2][64][20];
    __shared__ float Bs[2][16][72];

    const int tid  = threadIdx.x;
    const int lane = tid & 31, warp = tid >> 5;
    const int wm = warp >> 1, wn = warp & 1;        // 4 m-warps (16 rows) x 2 n-warps
    const int g  = lane >> 2, tg = lane & 3;
    const int bm = blockIdx.y * 64, bn = blockIdx.x * 64;

    const int am  = tid >> 2;           // 0..63, one cp16 per thread
    const int ak  = (tid & 3) * 4;
    const int bk  = tid >> 4;
    const int bnn = (tid & 15) * 4;

    float acc[4][4];
#pragma unroll
    for (int j = 0; j < 4; j++)
#pragma unroll
        for (int q = 0; q < 4; q++) acc[j][q] = 0.f;

    const int KT = K >> 4;

    {
        cp16(&As[0][am][ak], A + (size_t)(bm + am) * K + ak);
        cp16(&Bs[0][bk][bnn], B + (size_t)bk * N + bn + bnn);
        asm volatile("cp.async.commit_group;");
    }

    for (int kt = 0; kt < KT; kt++) {
        const int buf = kt & 1;
        if (kt + 1 < KT) {
            const int k0 = (kt + 1) << 4;
            cp16(&As[buf ^ 1][am][ak], A + (size_t)(bm + am) * K + k0 + ak);
            cp16(&Bs[buf ^ 1][bk][bnn], B + (size_t)(k0 + bk) * N + bn + bnn);
            asm volatile("cp.async.commit_group;");
            asm volatile("cp.async.wait_group 1;");
        } else {
            asm volatile("cp.async.wait_group 0;");
        }
        __syncthreads();

#pragma unroll
        for (int ks = 0; ks < 2; ks++) {
            const int k8 = ks * 8;
            const int mb = wm * 16;
            uint32_t ahi[4], alo[4];
            f32split(As[buf][mb + g    ][k8 + tg    ], ahi[0], alo[0]);
            f32split(As[buf][mb + g + 8][k8 + tg    ], ahi[1], alo[1]);
            f32split(As[buf][mb + g    ][k8 + tg + 4], ahi[2], alo[2]);
            f32split(As[buf][mb + g + 8][k8 + tg + 4], ahi[3], alo[3]);
            uint32_t bhi[4][2], blo[4][2];
#pragma unroll
            for (int nf = 0; nf < 4; nf++) {
                const int nb = wn * 32 + nf * 8;
                f32split(Bs[buf][k8 + tg    ][nb + g], bhi[nf][0], blo[nf][0]);
                f32split(Bs[buf][k8 + tg + 4][nb + g], bhi[nf][1], blo[nf][1]);
            }
#pragma unroll
            for (int nf = 0; nf < 4; nf++) mma8(acc[nf], ahi, bhi[nf]);
#pragma unroll
            for (int nf = 0; nf < 4; nf++) mma8(acc[nf], ahi, blo[nf]);
#pragma unroll
            for (int nf = 0; nf < 4; nf++) mma8(acc[nf], alo, bhi[nf]);
        }
        __syncthreads();
    }

#pragma unroll
    for (int nf = 0; nf < 4; nf++) {
        const int c0 = bn + wn * 32 + nf * 8 + 2 * tg;
#pragma unroll
        for (int half = 0; half < 2; half++) {
            const int r = bm + wm * 16 + g + half * 8;
            if (r < M) {
                float v0 = acc[nf][half * 2 + 0] + bias[c0];
                float v1 = acc[nf][half * 2 + 1] + bias[c0 + 1];
                if (RES) { v0 += Rsd[(size_t)r * N + c0]; v1 += Rsd[(size_t)r * N + c0 + 1]; }
                if (GELU) { v0 = gelu_f(v0); v1 = gelu_f(v1); }
                *reinterpret_cast<float2*>(&C[(size_t)r * N + c0]) = make_float2(v0, v1);
            }
        }
    }
}

// ---------------- attention ----------------
__global__ void attn_kernel(const float* __restrict__ QKV, float* __restrict__ ATT)
{
    __shared__ float Ks[65 * 97];
    __shared__ float Qs[4][96];
    __shared__ float Pw[4][68];
    int s = blockIdx.x;
    int h = blockIdx.y;
    int tid = threadIdx.x;
    int warp = tid >> 5, lane = tid & 31;

    int start, len;
    if (s < BQ) { start = QL * s; len = QL; }
    else        { start = BQ * QL + DSEQ * (s - BQ); len = DSEQ; }

    for (int idx = tid; idx < len * HD; idx += 128) {
        int r = idx / HD, c = idx % HD;
        Ks[r * 97 + c] = QKV[(size_t)(start + r) * QKVD + DMODEL + h * HD + c];
    }
    __syncthreads();

    const float scale = 0.10206207261596575f;

    for (int qi = warp; qi < len; qi += 4) {
        for (int c = lane; c < HD; c += 32)
            Qs[warp][c] = QKV[(size_t)(start + qi) * QKVD + h * HD + c];
        __syncwarp();

        float sj[3];
        float mx = -1e30f;
#pragma unroll
        for (int u = 0; u < 3; u++) {
            int j = lane + 32 * u;
            float d = 0.f;
            if (j < len) {
                const float* kr = &Ks[j * 97];
#pragma unroll
                for (int c = 0; c < HD; c++) d = fmaf(Qs[warp][c], kr[c], d);
                d *= scale;
                mx = fmaxf(mx, d);
            }
            sj[u] = d;
        }
        for (int o = 16; o > 0; o >>= 1) mx = fmaxf(mx, __shfl_xor_sync(0xffffffffu, mx, o));
        float sum = 0.f;
#pragma unroll
        for (int u = 0; u < 3; u++) {
            int j = lane + 32 * u;
            float p = 0.f;
            if (j < len) p = expf(sj[u] - mx);
            sj[u] = p; sum += p;
        }
        for (int o = 16; o > 0; o >>= 1) sum += __shfl_xor_sync(0xffffffffu, sum, o);
        float inv = 1.f / sum;
#pragma unroll
        for (int u = 0; u < 3; u++) {
            int j = lane + 32 * u;
            if (j < len) Pw[warp][j] = sj[u] * inv;
        }
        __syncwarp();

#pragma unroll
        for (int u = 0; u < 3; u++) {
            int dcol = lane + 32 * u;
            float acc = 0.f;
            for (int j = 0; j < len; j++)
                acc = fmaf(Pw[warp][j],
                           QKV[(size_t)(start + j) * QKVD + 2 * DMODEL + h * HD + dcol], acc);
            ATT[(size_t)(start + qi) * DMODEL + h * HD + dcol] = acc;
        }
        __syncwarp();
    }
}

// ---------------- layernorm ----------------
__global__ void ln_kernel(const float* __restrict__ in, const float* __restrict__ g,
                          const float* __restrict__ b, float* __restrict__ out)
{
    __shared__ float red[16];
    int r = blockIdx.x, tid = threadIdx.x;
    const float* x = in + (size_t)r * DMODEL;
    float v0 = x[tid], v1 = x[tid + 256], v2 = x[tid + 512];
    float s = v0 + v1 + v2;
    float ss = v0 * v0 + v1 * v1 + v2 * v2;
    for (int o = 16; o > 0; o >>= 1) {
        s  += __shfl_xor_sync(0xffffffffu, s, o);
        ss += __shfl_xor_sync(0xffffffffu, ss, o);
    }
    int warp = tid >> 5, lane = tid & 31;
    if (lane == 0) { red[warp] = s; red[warp + 8] = ss; }
    __syncthreads();
    if (tid < 32) {
        float a = (tid < 8) ? red[tid] : 0.f;
        float c = (tid < 8) ? red[tid + 8] : 0.f;
        for (int o = 4; o > 0; o >>= 1) {
            a += __shfl_xor_sync(0xffffffffu, a, o);
            c += __shfl_xor_sync(0xffffffffu, c, o);
        }
        if (tid == 0) { red[0] = a; red[1] = c; }
    }
    __syncthreads();
    float mean = red[0] * (1.f / DMODEL);
    float var  = red[1] * (1.f / DMODEL) - mean * mean;
    float inv  = rsqrtf(var + 1e-5f);
    float* o = out + (size_t)r * DMODEL;
    o[tid]       = (v0 - mean) * inv * g[tid]       + b[tid];
    o[tid + 256] = (v1 - mean) * inv * g[tid + 256] + b[tid + 256];
    o[tid + 512] = (v2 - mean) * inv * g[tid + 512] + b[tid + 512];
}

// ---------------- pooler ----------------
__global__ void pool_kernel(const float* __restrict__ X, const float* __restrict__ X0q,
                            const float* __restrict__ cls_topic,
                            const float* __restrict__ W, const float* __restrict__ bias,
                            const float* __restrict__ mixer, float* __restrict__ PV)
{
    int i = blockIdx.x, tid = threadIdx.x;
    __shared__ float xin[DMODEL];
    float mx = mixer[0];
    for (int k = tid; k < DMODEL; k += 256) {
        float pre, post;
        if (i < BQ) {
            pre  = X0q[(size_t)i * DMODEL + k];
            post = X[(size_t)(QL * i) * DMODEL + k];
        } else {
            pre  = cls_topic[k];
            post = X[(size_t)(BQ * QL + DSEQ * (i - BQ)) * DMODEL + k];
        }
        xin[k] = mx * pre + (1.f - mx) * post;
    }
    __syncthreads();
    for (int n = tid; n < DMODEL; n += 256) {
        const float* w = W + (size_t)n * DMODEL;
        float acc = bias[n];
        for (int k = 0; k < DMODEL; k++) acc = fmaf(xin[k], w[k], acc);
        PV[(size_t)i * DMODEL + n] = acc;
    }
}

// ---------------- normalize & scatter ----------------
__global__ void norm_kernel(const float* __restrict__ PV, float* __restrict__ out)
{
    __shared__ float red[8];
    int i = blockIdx.x, tid = threadIdx.x;
    const float* x = PV + (size_t)i * DMODEL;
    float ss = 0.f;
    for (int k = tid; k < DMODEL; k += 256) { float v = x[k]; ss += v * v; }
    for (int o = 16; o > 0; o >>= 1) ss += __shfl_xor_sync(0xffffffffu, ss, o);
    int warp = tid >> 5, lane = tid & 31;
    if (lane == 0) red[warp] = ss;
    __syncthreads();
    if (tid < 32) {
        float a = (tid < 8) ? red[tid] : 0.f;
        for (int o = 4; o > 0; o >>= 1) a += __shfl_xor_sync(0xffffffffu, a, o);
        if (tid == 0) red[0] = a;
    }
    __syncthreads();
    float inv = 1.f / (sqrtf(red[0]) + 1e-4f);
    float* dst = out + 16 + ((i < BQ) ? (size_t)i * DMODEL
                                      : (size_t)BQ * DMODEL + (size_t)(i - BQ) * DMODEL);
    for (int k = tid; k < DMODEL; k += 256) dst[k] = x[k] * inv;
}

__global__ void score_kernel(float* __restrict__ out)
{
    __shared__ float red[8];
    int b = blockIdx.x, tid = threadIdx.x;
    const float* q = out + 16 + (size_t)b * DMODEL;
    const float* d = out + 16 + (size_t)BQ * DMODEL + (size_t)b * DMODEL;
    float s = 0.f;
    for (int k = tid; k < DMODEL; k += 256) s = fmaf(q[k], d[k], s);
    for (int o = 16; o > 0; o >>= 1) s += __shfl_xor_sync(0xffffffffu, s, o);
    int warp = tid >> 5, lane = tid & 31;
    if (lane == 0) red[warp] = s;
    __syncthreads();
    if (tid == 0) {
        float t = 0.f;
        for (int w = 0; w < 8; w++) t += red[w];
        out[b] = 6.f * t;
    }
}

// ---------------- launch ----------------
extern "C" void kernel_launch(void* const* d_in, const int* in_sizes, int n_in,
                              void* d_out, int out_size)
{
    const float* emb       = (const float*)d_in[0];
    const float* pos_q     = (const float*)d_in[1];
    const float* pos_d     = (const float*)d_in[2];
    const float* cls_topic = (const float*)d_in[3];
    const float* mixer     = (const float*)d_in[4];
    const float* pw        = (const float*)d_in[5];
    const float* pb        = (const float*)d_in[6];
    const float* Wqkv      = (const float*)d_in[7];
    const float* bqkv      = (const float*)d_in[8];
    const float* Wo        = (const float*)d_in[9];
    const float* bo        = (const float*)d_in[10];
    const float* g1        = (const float*)d_in[11];
    const float* b1        = (const float*)d_in[12];
    const float* W1        = (const float*)d_in[13];
    const float* bf1       = (const float*)d_in[14];
    const float* W2        = (const float*)d_in[15];
    const float* bf2       = (const float*)d_in[16];
    const float* g2        = (const float*)d_in[17];
    const float* b2        = (const float*)d_in[18];
    const int*   query     = (const int*)d_in[19];
    const int*   document  = (const int*)d_in[20];
    float* out = (float*)d_out;

    float *X, *X0, *QKV, *ATT, *TMP, *Hb, *PV;
    cudaGetSymbolAddress((void**)&X,   g_X);
    cudaGetSymbolAddress((void**)&X0,  g_X0q);
    cudaGetSymbolAddress((void**)&QKV, g_QKV);
    cudaGetSymbolAddress((void**)&ATT, g_ATT);
    cudaGetSymbolAddress((void**)&TMP, g_TMP);
    cudaGetSymbolAddress((void**)&Hb,  g_H);
    cudaGetSymbolAddress((void**)&PV,  g_PV);

    embed_kernel<<<NTOK, 256>>>(emb, pos_q, pos_d, cls_topic, query, document, X, X0);

    const int MB128 = NTOKP / 128;   // 12
    const int MB64  = NTOKP / 64;    // 24
    for (int l = 0; l < 2; l++) {
        const float* wqkv = Wqkv + (size_t)l * DMODEL * QKVD;
        const float* wo   = Wo   + (size_t)l * DMODEL * DMODEL;
        const float* w1   = W1   + (size_t)l * DMODEL * FFD;
        const float* w2   = W2   + (size_t)l * FFD * DMODEL;

        gemm_tc128<false, false><<<dim3(QKVD / 64, MB128), 256>>>(
            X, wqkv, bqkv + (size_t)l * QKVD, nullptr, QKV, NTOK, QKVD, DMODEL);

        attn_kernel<<<dim3(32, NH), 128>>>(QKV, ATT);

        gemm_tc64<false, true><<<dim3(DMODEL / 64, MB64), 256>>>(
            ATT, wo, bo + (size_t)l * DMODEL, X, TMP, NTOK, DMODEL, DMODEL);

        ln_kernel<<<NTOK, 256>>>(TMP, g1 + (size_t)l * DMODEL, b1 + (size_t)l * DMODEL, X);

        gemm_tc128<true, false><<<dim3(FFD / 64, MB128), 256>>>(
            X, w1, bf1 + (size_t)l * FFD, nullptr, Hb, NTOK, FFD, DMODEL);

        gemm_tc64<false, true><<<dim3(DMODEL / 64, MB64), 256>>>(
            Hb, w2, bf2 + (size_t)l * DMODEL, X, TMP, NTOK, DMODEL, FFD);

        ln_kernel<<<NTOK, 256>>>(TMP, g2 + (size_t)l * DMODEL, b2 + (size_t)l * DMODEL, X);
    }

    pool_kernel<<<32, 256>>>(X, X0, cls_topic, pw, pb, mixer, PV);
    norm_kernel<<<32, 256>>>(PV, out);
    score_kernel<<<16, 256>>>(out);
}

// round 14
// speedup vs baseline: 1.5757x; 1.2794x over previous
#include <cuda_runtime.h>
#include <cuda_bf16.h>
#include <stdint.h>
#include <math.h>

// Problem constants
#define BQ     16
#define QL     30
#define DSEQ   65          // cls + 64 chunk tokens
#define NTOK   (BQ*QL + BQ*DSEQ)   // 1520
#define NTOKP  1536                 // padded to 12*128 tiles
#define DMODEL 768
#define NH     8
#define HD     96
#define FFD    3072
#define QKVD   2304

// ---------------- scratch (static device globals; padded rows are dead) ----------------
__device__ float g_X   [NTOKP * DMODEL];
__device__ float g_X0q [BQ * DMODEL];
__device__ float g_QKV [NTOKP * QKVD];
__device__ float g_ATT [NTOKP * DMODEL];
__device__ float g_TMP [NTOKP * DMODEL];
__device__ float g_H   [NTOKP * FFD];
__device__ float g_PV  [32 * DMODEL];

// ---------------- helpers ----------------
__device__ __forceinline__ void cp16(void* smem, const void* g) {
    uint32_t s = (uint32_t)__cvta_generic_to_shared(smem);
    asm volatile("cp.async.ca.shared.global [%0], [%1], 16;" :: "r"(s), "l"(g));
}
// mask-based tf32 split: hi = x with low 13 mantissa bits cleared (exact tf32),
// lo = x - hi (exact). mma.tf32 ignores operand bits [12:0], so no cvt needed.
__device__ __forceinline__ void fsplit(float x, uint32_t& hi, uint32_t& lo) {
    uint32_t h = __float_as_uint(x) & 0xffffe000u;
    hi = h;
    lo = __float_as_uint(x - __uint_as_float(h));
}
__device__ __forceinline__ void mma8(float* c, const uint32_t* a, const uint32_t* b) {
    asm volatile("mma.sync.aligned.m16n8k8.row.col.f32.tf32.tf32.f32 "
                 "{%0,%1,%2,%3}, {%4,%5,%6,%7}, {%8,%9}, {%0,%1,%2,%3};"
                 : "+f"(c[0]), "+f"(c[1]), "+f"(c[2]), "+f"(c[3])
                 : "r"(a[0]), "r"(a[1]), "r"(a[2]), "r"(a[3]),
                   "r"(b[0]), "r"(b[1]));
}
__device__ __forceinline__ float gelu_f(float x) {
    return 0.5f * x * (1.f + tanhf(0.7978845608028654f * (x + 0.044715f * x * x * x)));
}

// ---------------- embedding / sequence assembly ----------------
__global__ void embed_kernel(const float* __restrict__ emb,
                             const float* __restrict__ pos_q,
                             const float* __restrict__ pos_d,
                             const float* __restrict__ cls_topic,
                             const int*   __restrict__ query,
                             const int*   __restrict__ document,
                             float* __restrict__ X, float* __restrict__ X0q)
{
    int r = blockIdx.x;
    int tid = threadIdx.x;                  // 256 threads
    float* xr = X + (size_t)r * DMODEL;
    if (r < BQ * QL) {
        int b = r / QL, t = r % QL;
        const float* e = emb + (size_t)query[b * QL + t] * DMODEL;
        const float* p = pos_q + (size_t)t * DMODEL;
        for (int k = tid; k < DMODEL; k += 256) {
            float v = e[k] + p[k];
            xr[k] = v;
            if (t == 0) X0q[(size_t)b * DMODEL + k] = v;
        }
    } else {
        int rr = r - BQ * QL;
        int b = rr / DSEQ, p = rr % DSEQ;
        if (p == 0) {
            for (int k = tid; k < DMODEL; k += 256) xr[k] = cls_topic[k];
        } else if (p < 8) {
            for (int k = tid; k < DMODEL; k += 256) xr[k] = 0.f;
        } else {
            int t = p - 8;
            const float* e = emb + (size_t)document[b * 2000 + t] * DMODEL;
            const float* pp = pos_d + (size_t)t * DMODEL;
            for (int k = tid; k < DMODEL; k += 256) xr[k] = e[k] + pp[k];
        }
    }
}

// ---------------- tensor-core GEMM: 3xTF32 (round-6 structure, mask split) ----------
template<bool GELU, bool RES>
__global__ void __launch_bounds__(256)
gemm_tc(const float* __restrict__ A, const float* __restrict__ B,
        const float* __restrict__ bias, const float* __restrict__ Rsd,
        float* __restrict__ C, int M, int N, int K)
{
    __shared__ float As[2][128][20];   // [m][k], pad 4 -> conflict-free frag loads
    __shared__ float Bs[2][16][72];    // [k][n], pad 8 -> conflict-free frag loads

    const int tid  = threadIdx.x;
    const int lane = tid & 31, warp = tid >> 5;
    const int wm = warp >> 1, wn = warp & 1;        // 4 x 2 warps
    const int g  = lane >> 2, tg = lane & 3;
    const int bm = blockIdx.y * 128, bn = blockIdx.x * 64;

    const int am  = tid >> 2;           // A rows 0..63 (+64)
    const int ak  = (tid & 3) * 4;      // A k offset 0/4/8/12
    const int bk  = tid >> 4;           // B k 0..15
    const int bnn = (tid & 15) * 4;     // B n offset

    float acc[2][4][4];
#pragma unroll
    for (int i = 0; i < 2; i++)
#pragma unroll
        for (int j = 0; j < 4; j++)
#pragma unroll
            for (int q = 0; q < 4; q++) acc[i][j][q] = 0.f;

    const int KT = K >> 4;

    {   // prologue: stage 0
        const float* ap = A + (size_t)(bm + am) * K + ak;
        cp16(&As[0][am][ak],      ap);
        cp16(&As[0][am + 64][ak], ap + (size_t)64 * K);
        cp16(&Bs[0][bk][bnn],     B + (size_t)bk * N + bn + bnn);
        asm volatile("cp.async.commit_group;");
    }

    for (int kt = 0; kt < KT; kt++) {
        const int buf = kt & 1;
        if (kt + 1 < KT) {
            const int k0 = (kt + 1) << 4;
            const float* ap = A + (size_t)(bm + am) * K + k0 + ak;
            cp16(&As[buf ^ 1][am][ak],      ap);
            cp16(&As[buf ^ 1][am + 64][ak], ap + (size_t)64 * K);
            cp16(&Bs[buf ^ 1][bk][bnn],     B + (size_t)(k0 + bk) * N + bn + bnn);
            asm volatile("cp.async.commit_group;");
            asm volatile("cp.async.wait_group 1;");
        } else {
            asm volatile("cp.async.wait_group 0;");
        }
        __syncthreads();

#pragma unroll
        for (int ks = 0; ks < 2; ks++) {
            const int k8 = ks * 8;
            uint32_t ahi[2][4], alo[2][4];
#pragma unroll
            for (int mf = 0; mf < 2; mf++) {
                const int mb = wm * 32 + mf * 16;
                fsplit(As[buf][mb + g    ][k8 + tg    ], ahi[mf][0], alo[mf][0]);
                fsplit(As[buf][mb + g + 8][k8 + tg    ], ahi[mf][1], alo[mf][1]);
                fsplit(As[buf][mb + g    ][k8 + tg + 4], ahi[mf][2], alo[mf][2]);
                fsplit(As[buf][mb + g + 8][k8 + tg + 4], ahi[mf][3], alo[mf][3]);
            }
            uint32_t bhi[4][2], blo[4][2];
#pragma unroll
            for (int nf = 0; nf < 4; nf++) {
                const int nb = wn * 32 + nf * 8;
                fsplit(Bs[buf][k8 + tg    ][nb + g], bhi[nf][0], blo[nf][0]);
                fsplit(Bs[buf][k8 + tg + 4][nb + g], bhi[nf][1], blo[nf][1]);
            }
#pragma unroll
            for (int mf = 0; mf < 2; mf++)
#pragma unroll
                for (int nf = 0; nf < 4; nf++) {
                    mma8(acc[mf][nf], ahi[mf], bhi[nf]);
                    mma8(acc[mf][nf], ahi[mf], blo[nf]);
                    mma8(acc[mf][nf], alo[mf], bhi[nf]);
                }
        }
        __syncthreads();
    }

    // epilogue
#pragma unroll
    for (int mf = 0; mf < 2; mf++) {
#pragma unroll
        for (int nf = 0; nf < 4; nf++) {
            const int c0 = bn + wn * 32 + nf * 8 + 2 * tg;
#pragma unroll
            for (int half = 0; half < 2; half++) {
                const int r = bm + wm * 32 + mf * 16 + g + half * 8;
                if (r < M) {
                    float v0 = acc[mf][nf][half * 2 + 0] + bias[c0];
                    float v1 = acc[mf][nf][half * 2 + 1] + bias[c0 + 1];
                    if (RES) { v0 += Rsd[(size_t)r * N + c0]; v1 += Rsd[(size_t)r * N + c0 + 1]; }
                    if (GELU) { v0 = gelu_f(v0); v1 = gelu_f(v1); }
                    *reinterpret_cast<float2*>(&C[(size_t)r * N + c0]) = make_float2(v0, v1);
                }
            }
        }
    }
}

// ---------------- attention: K AND V staged in smem, pipelined AV ----------------
#define ATT_SMEM (2 * 65 * 97 * 4)

__global__ void attn_kernel(const float* __restrict__ QKV, float* __restrict__ ATT)
{
    extern __shared__ float sm[];
    float* Ks = sm;                 // [65][97]
    float* Vs = sm + 65 * 97;       // [65][97]
    __shared__ float Qs[4][96];
    __shared__ float Pw[4][68];
    int s = blockIdx.x;        // 0..31
    int h = blockIdx.y;        // 0..7
    int tid = threadIdx.x;     // 128
    int warp = tid >> 5, lane = tid & 31;

    int start, len;
    if (s < BQ) { start = QL * s; len = QL; }
    else        { start = BQ * QL + DSEQ * (s - BQ); len = DSEQ; }

    for (int idx = tid; idx < len * HD; idx += 128) {
        int r = idx / HD, c = idx % HD;
        const float* base = QKV + (size_t)(start + r) * QKVD + h * HD + c;
        Ks[r * 97 + c] = base[DMODEL];
        Vs[r * 97 + c] = base[2 * DMODEL];
    }
    __syncthreads();

    const float scale = 0.10206207261596575f;   // 1/sqrt(96)

    for (int qi = warp; qi < len; qi += 4) {
        for (int c = lane; c < HD; c += 32)
            Qs[warp][c] = QKV[(size_t)(start + qi) * QKVD + h * HD + c];
        __syncwarp();

        float sj[3];
        float mx = -1e30f;
#pragma unroll
        for (int u = 0; u < 3; u++) {
            int j = lane + 32 * u;
            float d = 0.f;
            if (j < len) {
                const float* kr = &Ks[j * 97];
#pragma unroll
                for (int c = 0; c < HD; c++) d = fmaf(Qs[warp][c], kr[c], d);
                d *= scale;
                mx = fmaxf(mx, d);
            }
            sj[u] = d;
        }
        for (int o = 16; o > 0; o >>= 1) mx = fmaxf(mx, __shfl_xor_sync(0xffffffffu, mx, o));
        float sum = 0.f;
#pragma unroll
        for (int u = 0; u < 3; u++) {
            int j = lane + 32 * u;
            float p = 0.f;
            if (j < len) p = expf(sj[u] - mx);
            sj[u] = p; sum += p;
        }
        for (int o = 16; o > 0; o >>= 1) sum += __shfl_xor_sync(0xffffffffu, sum, o);
        float inv = 1.f / sum;
#pragma unroll
        for (int u = 0; u < 3; u++) {
            int j = lane + 32 * u;
            if (j < len) Pw[warp][j] = sj[u] * inv;
        }
        __syncwarp();

        // AV from smem, 2 independent partial accumulators per output column
#pragma unroll
        for (int u = 0; u < 3; u++) {
            int dcol = lane + 32 * u;
            float a0 = 0.f, a1 = 0.f;
            int j = 0;
#pragma unroll 4
            for (; j + 1 < len; j += 2) {
                a0 = fmaf(Pw[warp][j],     Vs[j * 97 + dcol],       a0);
                a1 = fmaf(Pw[warp][j + 1], Vs[(j + 1) * 97 + dcol], a1);
            }
            if (j < len) a0 = fmaf(Pw[warp][j], Vs[j * 97 + dcol], a0);
            ATT[(size_t)(start + qi) * DMODEL + h * HD + dcol] = a0 + a1;
        }
        __syncwarp();
    }
}

// ---------------- layernorm: one block per row ----------------
__global__ void ln_kernel(const float* __restrict__ in, const float* __restrict__ g,
                          const float* __restrict__ b, float* __restrict__ out)
{
    __shared__ float red[16];
    int r = blockIdx.x, tid = threadIdx.x;   // 256 threads
    const float* x = in + (size_t)r * DMODEL;
    float v0 = x[tid], v1 = x[tid + 256], v2 = x[tid + 512];
    float s = v0 + v1 + v2;
    float ss = v0 * v0 + v1 * v1 + v2 * v2;
    for (int o = 16; o > 0; o >>= 1) {
        s  += __shfl_xor_sync(0xffffffffu, s, o);
        ss += __shfl_xor_sync(0xffffffffu, ss, o);
    }
    int warp = tid >> 5, lane = tid & 31;
    if (lane == 0) { red[warp] = s; red[warp + 8] = ss; }
    __syncthreads();
    if (tid < 32) {
        float a = (tid < 8) ? red[tid] : 0.f;
        float c = (tid < 8) ? red[tid + 8] : 0.f;
        for (int o = 4; o > 0; o >>= 1) {
            a += __shfl_xor_sync(0xffffffffu, a, o);
            c += __shfl_xor_sync(0xffffffffu, c, o);
        }
        if (tid == 0) { red[0] = a; red[1] = c; }
    }
    __syncthreads();
    float mean = red[0] * (1.f / DMODEL);
    float var  = red[1] * (1.f / DMODEL) - mean * mean;
    float inv  = rsqrtf(var + 1e-5f);
    float* o = out + (size_t)r * DMODEL;
    o[tid]       = (v0 - mean) * inv * g[tid]       + b[tid];
    o[tid + 256] = (v1 - mean) * inv * g[tid + 256] + b[tid + 256];
    o[tid + 512] = (v2 - mean) * inv * g[tid + 512] + b[tid + 512];
}

// ---------------- pooler ----------------
__global__ void pool_kernel(const float* __restrict__ X, const float* __restrict__ X0q,
                            const float* __restrict__ cls_topic,
                            const float* __restrict__ W, const float* __restrict__ bias,
                            const float* __restrict__ mixer, float* __restrict__ PV)
{
    int i = blockIdx.x, tid = threadIdx.x;  // 32 blocks x 256
    __shared__ float xin[DMODEL];
    float mx = mixer[0];
    for (int k = tid; k < DMODEL; k += 256) {
        float pre, post;
        if (i < BQ) {
            pre  = X0q[(size_t)i * DMODEL + k];
            post = X[(size_t)(QL * i) * DMODEL + k];
        } else {
            pre  = cls_topic[k];
            post = X[(size_t)(BQ * QL + DSEQ * (i - BQ)) * DMODEL + k];
        }
        xin[k] = mx * pre + (1.f - mx) * post;
    }
    __syncthreads();
    for (int n = tid; n < DMODEL; n += 256) {
        const float* w = W + (size_t)n * DMODEL;
        float acc = bias[n];
        for (int k = 0; k < DMODEL; k++) acc = fmaf(xin[k], w[k], acc);
        PV[(size_t)i * DMODEL + n] = acc;
    }
}

// ---------------- normalize & scatter ----------------
__global__ void norm_kernel(const float* __restrict__ PV, float* __restrict__ out)
{
    __shared__ float red[8];
    int i = blockIdx.x, tid = threadIdx.x;  // 32 blocks x 256
    const float* x = PV + (size_t)i * DMODEL;
    float ss = 0.f;
    for (int k = tid; k < DMODEL; k += 256) { float v = x[k]; ss += v * v; }
    for (int o = 16; o > 0; o >>= 1) ss += __shfl_xor_sync(0xffffffffu, ss, o);
    int warp = tid >> 5, lane = tid & 31;
    if (lane == 0) red[warp] = ss;
    __syncthreads();
    if (tid < 32) {
        float a = (tid < 8) ? red[tid] : 0.f;
        for (int o = 4; o > 0; o >>= 1) a += __shfl_xor_sync(0xffffffffu, a, o);
        if (tid == 0) red[0] = a;
    }
    __syncthreads();
    float inv = 1.f / (sqrtf(red[0]) + 1e-4f);
    float* dst = out + 16 + ((i < BQ) ? (size_t)i * DMODEL
                                      : (size_t)BQ * DMODEL + (size_t)(i - BQ) * DMODEL);
    for (int k = tid; k < DMODEL; k += 256) dst[k] = x[k] * inv;
}

__global__ void score_kernel(float* __restrict__ out)
{
    __shared__ float red[8];
    int b = blockIdx.x, tid = threadIdx.x;  // 16 blocks x 256
    const float* q = out + 16 + (size_t)b * DMODEL;
    const float* d = out + 16 + (size_t)BQ * DMODEL + (size_t)b * DMODEL;
    float s = 0.f;
    for (int k = tid; k < DMODEL; k += 256) s = fmaf(q[k], d[k], s);
    for (int o = 16; o > 0; o >>= 1) s += __shfl_xor_sync(0xffffffffu, s, o);
    int warp = tid >> 5, lane = tid & 31;
    if (lane == 0) red[warp] = s;
    __syncthreads();
    if (tid == 0) {
        float t = 0.f;
        for (int w = 0; w < 8; w++) t += red[w];
        out[b] = 6.f * t;
    }
}

// ---------------- launch ----------------
extern "C" void kernel_launch(void* const* d_in, const int* in_sizes, int n_in,
                              void* d_out, int out_size)
{
    const float* emb       = (const float*)d_in[0];
    const float* pos_q     = (const float*)d_in[1];
    const float* pos_d     = (const float*)d_in[2];
    const float* cls_topic = (const float*)d_in[3];
    const float* mixer     = (const float*)d_in[4];
    const float* pw        = (const float*)d_in[5];
    const float* pb        = (const float*)d_in[6];
    const float* Wqkv      = (const float*)d_in[7];
    const float* bqkv      = (const float*)d_in[8];
    const float* Wo        = (const float*)d_in[9];
    const float* bo        = (const float*)d_in[10];
    const float* g1        = (const float*)d_in[11];
    const float* b1        = (const float*)d_in[12];
    const float* W1        = (const float*)d_in[13];
    const float* bf1       = (const float*)d_in[14];
    const float* W2        = (const float*)d_in[15];
    const float* bf2       = (const float*)d_in[16];
    const float* g2        = (const float*)d_in[17];
    const float* b2        = (const float*)d_in[18];
    const int*   query     = (const int*)d_in[19];
    const int*   document  = (const int*)d_in[20];
    float* out = (float*)d_out;

    float *X, *X0, *QKV, *ATT, *TMP, *Hb, *PV;
    cudaGetSymbolAddress((void**)&X,   g_X);
    cudaGetSymbolAddress((void**)&X0,  g_X0q);
    cudaGetSymbolAddress((void**)&QKV, g_QKV);
    cudaGetSymbolAddress((void**)&ATT, g_ATT);
    cudaGetSymbolAddress((void**)&TMP, g_TMP);
    cudaGetSymbolAddress((void**)&Hb,  g_H);
    cudaGetSymbolAddress((void**)&PV,  g_PV);

    // raise dynamic smem limit for attention (host-side attribute; idempotent)
    cudaFuncSetAttribute(attn_kernel, cudaFuncAttributeMaxDynamicSharedMemorySize, ATT_SMEM);

    embed_kernel<<<NTOK, 256>>>(emb, pos_q, pos_d, cls_topic, query, document, X, X0);

    const int MB = NTOKP / 128;   // 12
    for (int l = 0; l < 2; l++) {
        const float* wqkv = Wqkv + (size_t)l * DMODEL * QKVD;
        const float* wo   = Wo   + (size_t)l * DMODEL * DMODEL;
        const float* w1   = W1   + (size_t)l * DMODEL * FFD;
        const float* w2   = W2   + (size_t)l * FFD * DMODEL;

        gemm_tc<false, false><<<dim3(QKVD / 64, MB), 256>>>(
            X, wqkv, bqkv + (size_t)l * QKVD, nullptr, QKV, NTOK, QKVD, DMODEL);

        attn_kernel<<<dim3(32, NH), 128, ATT_SMEM>>>(QKV, ATT);

        gemm_tc<false, true><<<dim3(DMODEL / 64, MB), 256>>>(
            ATT, wo, bo + (size_t)l * DMODEL, X, TMP, NTOK, DMODEL, DMODEL);

        ln_kernel<<<NTOK, 256>>>(TMP, g1 + (size_t)l * DMODEL, b1 + (size_t)l * DMODEL, X);

        gemm_tc<true, false><<<dim3(FFD / 64, MB), 256>>>(
            X, w1, bf1 + (size_t)l * FFD, nullptr, Hb, NTOK, FFD, DMODEL);

        gemm_tc<false, true><<<dim3(DMODEL / 64, MB), 256>>>(
            Hb, w2, bf2 + (size_t)l * DMODEL, X, TMP, NTOK, DMODEL, FFD);

        ln_kernel<<<NTOK, 256>>>(TMP, g2 + (size_t)l * DMODEL, b2 + (size_t)l * DMODEL, X);
    }

    pool_kernel<<<32, 256>>>(X, X0, cls_topic, pw, pb, mixer, PV);
    norm_kernel<<<32, 256>>>(PV, out);
    score_kernel<<<16, 256>>>(out);
}

// round 15
// speedup vs baseline: 1.5773x; 1.0010x over previous
#include <cuda_runtime.h>
#include <cuda_bf16.h>
#include <stdint.h>
#include <math.h>

// Problem constants
#define BQ     16
#define QL     30
#define DSEQ   65          // cls + 64 chunk tokens
#define NTOK   (BQ*QL + BQ*DSEQ)   // 1520
#define NTOKP  1536                 // padded to 12*128 tiles
#define DMODEL 768
#define NH     8
#define HD     96
#define FFD    3072
#define QKVD   2304

// ---------------- scratch (static device globals; padded rows are dead) ----------------
__device__ float g_X   [NTOKP * DMODEL];
__device__ float g_X0q [BQ * DMODEL];
__device__ float g_QKV [NTOKP * QKVD];
__device__ float g_ATT [NTOKP * DMODEL];
__device__ float g_TMP [NTOKP * DMODEL];
__device__ float g_H   [NTOKP * FFD];
__device__ float g_PV  [32 * DMODEL];

// ---------------- helpers ----------------
__device__ __forceinline__ void cp16(void* smem, const void* g) {
    uint32_t s = (uint32_t)__cvta_generic_to_shared(smem);
    asm volatile("cp.async.ca.shared.global [%0], [%1], 16;" :: "r"(s), "l"(g));
}
// mask-based tf32 split: hi = x with low 13 mantissa bits cleared (exact tf32),
// lo = x - hi (exact). mma.tf32 ignores operand bits [12:0], so no cvt needed.
__device__ __forceinline__ void fsplit(float x, uint32_t& hi, uint32_t& lo) {
    uint32_t h = __float_as_uint(x) & 0xffffe000u;
    hi = h;
    lo = __float_as_uint(x - __uint_as_float(h));
}
__device__ __forceinline__ void mma8(float* c, const uint32_t* a, const uint32_t* b) {
    asm volatile("mma.sync.aligned.m16n8k8.row.col.f32.tf32.tf32.f32 "
                 "{%0,%1,%2,%3}, {%4,%5,%6,%7}, {%8,%9}, {%0,%1,%2,%3};"
                 : "+f"(c[0]), "+f"(c[1]), "+f"(c[2]), "+f"(c[3])
                 : "r"(a[0]), "r"(a[1]), "r"(a[2]), "r"(a[3]),
                   "r"(b[0]), "r"(b[1]));
}
__device__ __forceinline__ float gelu_f(float x) {
    return 0.5f * x * (1.f + tanhf(0.7978845608028654f * (x + 0.044715f * x * x * x)));
}

// ---------------- embedding / sequence assembly ----------------
__global__ void embed_kernel(const float* __restrict__ emb,
                             const float* __restrict__ pos_q,
                             const float* __restrict__ pos_d,
                             const float* __restrict__ cls_topic,
                             const int*   __restrict__ query,
                             const int*   __restrict__ document,
                             float* __restrict__ X, float* __restrict__ X0q)
{
    int r = blockIdx.x;
    int tid = threadIdx.x;                  // 256 threads
    float* xr = X + (size_t)r * DMODEL;
    if (r < BQ * QL) {
        int b = r / QL, t = r % QL;
        const float* e = emb + (size_t)query[b * QL + t] * DMODEL;
        const float* p = pos_q + (size_t)t * DMODEL;
        for (int k = tid; k < DMODEL; k += 256) {
            float v = e[k] + p[k];
            xr[k] = v;
            if (t == 0) X0q[(size_t)b * DMODEL + k] = v;
        }
    } else {
        int rr = r - BQ * QL;
        int b = rr / DSEQ, p = rr % DSEQ;
        if (p == 0) {
            for (int k = tid; k < DMODEL; k += 256) xr[k] = cls_topic[k];
        } else if (p < 8) {
            for (int k = tid; k < DMODEL; k += 256) xr[k] = 0.f;
        } else {
            int t = p - 8;
            const float* e = emb + (size_t)document[b * 2000 + t] * DMODEL;
            const float* pp = pos_d + (size_t)t * DMODEL;
            for (int k = tid; k < DMODEL; k += 256) xr[k] = e[k] + pp[k];
        }
    }
}

// ---------------- tensor-core GEMM: 3xTF32, mask split, pass-major mma order --------
template<bool GELU, bool RES>
__global__ void __launch_bounds__(256)
gemm_tc(const float* __restrict__ A, const float* __restrict__ B,
        const float* __restrict__ bias, const float* __restrict__ Rsd,
        float* __restrict__ C, int M, int N, int K)
{
    __shared__ float As[2][128][20];   // [m][k], pad 4 -> conflict-free frag loads
    __shared__ float Bs[2][16][72];    // [k][n], pad 8 -> conflict-free frag loads

    const int tid  = threadIdx.x;
    const int lane = tid & 31, warp = tid >> 5;
    const int wm = warp >> 1, wn = warp & 1;        // 4 x 2 warps
    const int g  = lane >> 2, tg = lane & 3;
    const int bm = blockIdx.y * 128, bn = blockIdx.x * 64;

    const int am  = tid >> 2;           // A rows 0..63 (+64)
    const int ak  = (tid & 3) * 4;      // A k offset 0/4/8/12
    const int bk  = tid >> 4;           // B k 0..15
    const int bnn = (tid & 15) * 4;     // B n offset

    float acc[2][4][4];
#pragma unroll
    for (int i = 0; i < 2; i++)
#pragma unroll
        for (int j = 0; j < 4; j++)
#pragma unroll
            for (int q = 0; q < 4; q++) acc[i][j][q] = 0.f;

    const int KT = K >> 4;

    {   // prologue: stage 0
        const float* ap = A + (size_t)(bm + am) * K + ak;
        cp16(&As[0][am][ak],      ap);
        cp16(&As[0][am + 64][ak], ap + (size_t)64 * K);
        cp16(&Bs[0][bk][bnn],     B + (size_t)bk * N + bn + bnn);
        asm volatile("cp.async.commit_group;");
    }

    for (int kt = 0; kt < KT; kt++) {
        const int buf = kt & 1;
        if (kt + 1 < KT) {
            const int k0 = (kt + 1) << 4;
            const float* ap = A + (size_t)(bm + am) * K + k0 + ak;
            cp16(&As[buf ^ 1][am][ak],      ap);
            cp16(&As[buf ^ 1][am + 64][ak], ap + (size_t)64 * K);
            cp16(&Bs[buf ^ 1][bk][bnn],     B + (size_t)(k0 + bk) * N + bn + bnn);
            asm volatile("cp.async.commit_group;");
            asm volatile("cp.async.wait_group 1;");
        } else {
            asm volatile("cp.async.wait_group 0;");
        }
        __syncthreads();

#pragma unroll
        for (int ks = 0; ks < 2; ks++) {
            const int k8 = ks * 8;
            uint32_t ahi[2][4], alo[2][4];
#pragma unroll
            for (int mf = 0; mf < 2; mf++) {
                const int mb = wm * 32 + mf * 16;
                fsplit(As[buf][mb + g    ][k8 + tg    ], ahi[mf][0], alo[mf][0]);
                fsplit(As[buf][mb + g + 8][k8 + tg    ], ahi[mf][1], alo[mf][1]);
                fsplit(As[buf][mb + g    ][k8 + tg + 4], ahi[mf][2], alo[mf][2]);
                fsplit(As[buf][mb + g + 8][k8 + tg + 4], ahi[mf][3], alo[mf][3]);
            }
            uint32_t bhi[4][2], blo[4][2];
#pragma unroll
            for (int nf = 0; nf < 4; nf++) {
                const int nb = wn * 32 + nf * 8;
                fsplit(Bs[buf][k8 + tg    ][nb + g], bhi[nf][0], blo[nf][0]);
                fsplit(Bs[buf][k8 + tg + 4][nb + g], bhi[nf][1], blo[nf][1]);
            }
            // pass-major: dependent updates to each acc spaced by 8 independent mmas.
            // Per-acc accumulation order preserved (hi*hi, hi*lo, lo*hi) -> bitwise identical.
#pragma unroll
            for (int mf = 0; mf < 2; mf++)
#pragma unroll
                for (int nf = 0; nf < 4; nf++) mma8(acc[mf][nf], ahi[mf], bhi[nf]);
#pragma unroll
            for (int mf = 0; mf < 2; mf++)
#pragma unroll
                for (int nf = 0; nf < 4; nf++) mma8(acc[mf][nf], ahi[mf], blo[nf]);
#pragma unroll
            for (int mf = 0; mf < 2; mf++)
#pragma unroll
                for (int nf = 0; nf < 4; nf++) mma8(acc[mf][nf], alo[mf], bhi[nf]);
        }
        __syncthreads();
    }

    // epilogue
#pragma unroll
    for (int mf = 0; mf < 2; mf++) {
#pragma unroll
        for (int nf = 0; nf < 4; nf++) {
            const int c0 = bn + wn * 32 + nf * 8 + 2 * tg;
#pragma unroll
            for (int half = 0; half < 2; half++) {
                const int r = bm + wm * 32 + mf * 16 + g + half * 8;
                if (r < M) {
                    float v0 = acc[mf][nf][half * 2 + 0] + bias[c0];
                    float v1 = acc[mf][nf][half * 2 + 1] + bias[c0 + 1];
                    if (RES) { v0 += Rsd[(size_t)r * N + c0]; v1 += Rsd[(size_t)r * N + c0 + 1]; }
                    if (GELU) { v0 = gelu_f(v0); v1 = gelu_f(v1); }
                    *reinterpret_cast<float2*>(&C[(size_t)r * N + c0]) = make_float2(v0, v1);
                }
            }
        }
    }
}

// ---------------- attention: K AND V staged in smem, pipelined AV ----------------
#define ATT_SMEM (2 * 65 * 97 * 4)

__global__ void attn_kernel(const float* __restrict__ QKV, float* __restrict__ ATT)
{
    extern __shared__ float sm[];
    float* Ks = sm;                 // [65][97]
    float* Vs = sm + 65 * 97;       // [65][97]
    __shared__ float Qs[4][96];
    __shared__ float Pw[4][68];
    int s = blockIdx.x;        // 0..31
    int h = blockIdx.y;        // 0..7
    int tid = threadIdx.x;     // 128
    int warp = tid >> 5, lane = tid & 31;

    int start, len;
    if (s < BQ) { start = QL * s; len = QL; }
    else        { start = BQ * QL + DSEQ * (s - BQ); len = DSEQ; }

    for (int idx = tid; idx < len * HD; idx += 128) {
        int r = idx / HD, c = idx % HD;
        const float* base = QKV + (size_t)(start + r) * QKVD + h * HD + c;
        Ks[r * 97 + c] = base[DMODEL];
        Vs[r * 97 + c] = base[2 * DMODEL];
    }
    __syncthreads();

    const float scale = 0.10206207261596575f;   // 1/sqrt(96)

    for (int qi = warp; qi < len; qi += 4) {
        for (int c = lane; c < HD; c += 32)
            Qs[warp][c] = QKV[(size_t)(start + qi) * QKVD + h * HD + c];
        __syncwarp();

        float sj[3];
        float mx = -1e30f;
#pragma unroll
        for (int u = 0; u < 3; u++) {
            int j = lane + 32 * u;
            float d = 0.f;
            if (j < len) {
                const float* kr = &Ks[j * 97];
#pragma unroll
                for (int c = 0; c < HD; c++) d = fmaf(Qs[warp][c], kr[c], d);
                d *= scale;
                mx = fmaxf(mx, d);
            }
            sj[u] = d;
        }
        for (int o = 16; o > 0; o >>= 1) mx = fmaxf(mx, __shfl_xor_sync(0xffffffffu, mx, o));
        float sum = 0.f;
#pragma unroll
        for (int u = 0; u < 3; u++) {
            int j = lane + 32 * u;
            float p = 0.f;
            if (j < len) p = expf(sj[u] - mx);
            sj[u] = p; sum += p;
        }
        for (int o = 16; o > 0; o >>= 1) sum += __shfl_xor_sync(0xffffffffu, sum, o);
        float inv = 1.f / sum;
#pragma unroll
        for (int u = 0; u < 3; u++) {
            int j = lane + 32 * u;
            if (j < len) Pw[warp][j] = sj[u] * inv;
        }
        __syncwarp();

        // AV from smem, 2 independent partial accumulators per output column
#pragma unroll
        for (int u = 0; u < 3; u++) {
            int dcol = lane + 32 * u;
            float a0 = 0.f, a1 = 0.f;
            int j = 0;
#pragma unroll 4
            for (; j + 1 < len; j += 2) {
                a0 = fmaf(Pw[warp][j],     Vs[j * 97 + dcol],       a0);
                a1 = fmaf(Pw[warp][j + 1], Vs[(j + 1) * 97 + dcol], a1);
            }
            if (j < len) a0 = fmaf(Pw[warp][j], Vs[j * 97 + dcol], a0);
            ATT[(size_t)(start + qi) * DMODEL + h * HD + dcol] = a0 + a1;
        }
        __syncwarp();
    }
}

// ---------------- layernorm: one block per row ----------------
__global__ void ln_kernel(const float* __restrict__ in, const float* __restrict__ g,
                          const float* __restrict__ b, float* __restrict__ out)
{
    __shared__ float red[16];
    int r = blockIdx.x, tid = threadIdx.x;   // 256 threads
    const float* x = in + (size_t)r * DMODEL;
    float v0 = x[tid], v1 = x[tid + 256], v2 = x[tid + 512];
    float s = v0 + v1 + v2;
    float ss = v0 * v0 + v1 * v1 + v2 * v2;
    for (int o = 16; o > 0; o >>= 1) {
        s  += __shfl_xor_sync(0xffffffffu, s, o);
        ss += __shfl_xor_sync(0xffffffffu, ss, o);
    }
    int warp = tid >> 5, lane = tid & 31;
    if (lane == 0) { red[warp] = s; red[warp + 8] = ss; }
    __syncthreads();
    if (tid < 32) {
        float a = (tid < 8) ? red[tid] : 0.f;
        float c = (tid < 8) ? red[tid + 8] : 0.f;
        for (int o = 4; o > 0; o >>= 1) {
            a += __shfl_xor_sync(0xffffffffu, a, o);
            c += __shfl_xor_sync(0xffffffffu, c, o);
        }
        if (tid == 0) { red[0] = a; red[1] = c; }
    }
    __syncthreads();
    float mean = red[0] * (1.f / DMODEL);
    float var  = red[1] * (1.f / DMODEL) - mean * mean;
    float inv  = rsqrtf(var + 1e-5f);
    float* o = out + (size_t)r * DMODEL;
    o[tid]       = (v0 - mean) * inv * g[tid]       + b[tid];
    o[tid + 256] = (v1 - mean) * inv * g[tid + 256] + b[tid + 256];
    o[tid + 512] = (v2 - mean) * inv * g[tid + 512] + b[tid + 512];
}

// ---------------- pooler ----------------
__global__ void pool_kernel(const float* __restrict__ X, const float* __restrict__ X0q,
                            const float* __restrict__ cls_topic,
                            const float* __restrict__ W, const float* __restrict__ bias,
                            const float* __restrict__ mixer, float* __restrict__ PV)
{
    int i = blockIdx.x, tid = threadIdx.x;  // 32 blocks x 256
    __shared__ float xin[DMODEL];
    float mx = mixer[0];
    for (int k = tid; k < DMODEL; k += 256) {
        float pre, post;
        if (i < BQ) {
            pre  = X0q[(size_t)i * DMODEL + k];
            post = X[(size_t)(QL * i) * DMODEL + k];
        } else {
            pre  = cls_topic[k];
            post = X[(size_t)(BQ * QL + DSEQ * (i - BQ)) * DMODEL + k];
        }
        xin[k] = mx * pre + (1.f - mx) * post;
    }
    __syncthreads();
    for (int n = tid; n < DMODEL; n += 256) {
        const float* w = W + (size_t)n * DMODEL;
        float acc = bias[n];
        for (int k = 0; k < DMODEL; k++) acc = fmaf(xin[k], w[k], acc);
        PV[(size_t)i * DMODEL + n] = acc;
    }
}

// ---------------- normalize & scatter ----------------
__global__ void norm_kernel(const float* __restrict__ PV, float* __restrict__ out)
{
    __shared__ float red[8];
    int i = blockIdx.x, tid = threadIdx.x;  // 32 blocks x 256
    const float* x = PV + (size_t)i * DMODEL;
    float ss = 0.f;
    for (int k = tid; k < DMODEL; k += 256) { float v = x[k]; ss += v * v; }
    for (int o = 16; o > 0; o >>= 1) ss += __shfl_xor_sync(0xffffffffu, ss, o);
    int warp = tid >> 5, lane = tid & 31;
    if (lane == 0) red[warp] = ss;
    __syncthreads();
    if (tid < 32) {
        float a = (tid < 8) ? red[tid] : 0.f;
        for (int o = 4; o > 0; o >>= 1) a += __shfl_xor_sync(0xffffffffu, a, o);
        if (tid == 0) red[0] = a;
    }
    __syncthreads();
    float inv = 1.f / (sqrtf(red[0]) + 1e-4f);
    float* dst = out + 16 + ((i < BQ) ? (size_t)i * DMODEL
                                      : (size_t)BQ * DMODEL + (size_t)(i - BQ) * DMODEL);
    for (int k = tid; k < DMODEL; k += 256) dst[k] = x[k] * inv;
}

__global__ void score_kernel(float* __restrict__ out)
{
    __shared__ float red[8];
    int b = blockIdx.x, tid = threadIdx.x;  // 16 blocks x 256
    const float* q = out + 16 + (size_t)b * DMODEL;
    const float* d = out + 16 + (size_t)BQ * DMODEL + (size_t)b * DMODEL;
    float s = 0.f;
    for (int k = tid; k < DMODEL; k += 256) s = fmaf(q[k], d[k], s);
    for (int o = 16; o > 0; o >>= 1) s += __shfl_xor_sync(0xffffffffu, s, o);
    int warp = tid >> 5, lane = tid & 31;
    if (lane == 0) red[warp] = s;
    __syncthreads();
    if (tid == 0) {
        float t = 0.f;
        for (int w = 0; w < 8; w++) t += red[w];
        out[b] = 6.f * t;
    }
}

// ---------------- launch ----------------
extern "C" void kernel_launch(void* const* d_in, const int* in_sizes, int n_in,
                              void* d_out, int out_size)
{
    const float* emb       = (const float*)d_in[0];
    const float* pos_q     = (const float*)d_in[1];
    const float* pos_d     = (const float*)d_in[2];
    const float* cls_topic = (const float*)d_in[3];
    const float* mixer     = (const float*)d_in[4];
    const float* pw        = (const float*)d_in[5];
    const float* pb        = (const float*)d_in[6];
    const float* Wqkv      = (const float*)d_in[7];
    const float* bqkv      = (const float*)d_in[8];
    const float* Wo        = (const float*)d_in[9];
    const float* bo        = (const float*)d_in[10];
    const float* g1        = (const float*)d_in[11];
    const float* b1        = (const float*)d_in[12];
    const float* W1        = (const float*)d_in[13];
    const float* bf1       = (const float*)d_in[14];
    const float* W2        = (const float*)d_in[15];
    const float* bf2       = (const float*)d_in[16];
    const float* g2        = (const float*)d_in[17];
    const float* b2        = (const float*)d_in[18];
    const int*   query     = (const int*)d_in[19];
    const int*   document  = (const int*)d_in[20];
    float* out = (float*)d_out;

    float *X, *X0, *QKV, *ATT, *TMP, *Hb, *PV;
    cudaGetSymbolAddress((void**)&X,   g_X);
    cudaGetSymbolAddress((void**)&X0,  g_X0q);
    cudaGetSymbolAddress((void**)&QKV, g_QKV);
    cudaGetSymbolAddress((void**)&ATT, g_ATT);
    cudaGetSymbolAddress((void**)&TMP, g_TMP);
    cudaGetSymbolAddress((void**)&Hb,  g_H);
    cudaGetSymbolAddress((void**)&PV,  g_PV);

    // raise dynamic smem limit for attention (host-side attribute; idempotent)
    cudaFuncSetAttribute(attn_kernel, cudaFuncAttributeMaxDynamicSharedMemorySize, ATT_SMEM);

    embed_kernel<<<NTOK, 256>>>(emb, pos_q, pos_d, cls_topic, query, document, X, X0);

    const int MB = NTOKP / 128;   // 12
    for (int l = 0; l < 2; l++) {
        const float* wqkv = Wqkv + (size_t)l * DMODEL * QKVD;
        const float* wo   = Wo   + (size_t)l * DMODEL * DMODEL;
        const float* w1   = W1   + (size_t)l * DMODEL * FFD;
        const float* w2   = W2   + (size_t)l * FFD * DMODEL;

        gemm_tc<false, false><<<dim3(QKVD / 64, MB), 256>>>(
            X, wqkv, bqkv + (size_t)l * QKVD, nullptr, QKV, NTOK, QKVD, DMODEL);

        attn_kernel<<<dim3(32, NH), 128, ATT_SMEM>>>(QKV, ATT);

        gemm_tc<false, true><<<dim3(DMODEL / 64, MB), 256>>>(
            ATT, wo, bo + (size_t)l * DMODEL, X, TMP, NTOK, DMODEL, DMODEL);

        ln_kernel<<<NTOK, 256>>>(TMP, g1 + (size_t)l * DMODEL, b1 + (size_t)l * DMODEL, X);

        gemm_tc<true, false><<<dim3(FFD / 64, MB), 256>>>(
            X, w1, bf1 + (size_t)l * FFD, nullptr, Hb, NTOK, FFD, DMODEL);

        gemm_tc<false, true><<<dim3(DMODEL / 64, MB), 256>>>(
            Hb, w2, bf2 + (size_t)l * DMODEL, X, TMP, NTOK, DMODEL, FFD);

        ln_kernel<<<NTOK, 256>>>(TMP, g2 + (size_t)l * DMODEL, b2 + (size_t)l * DMODEL, X);
    }

    pool_kernel<<<32, 256>>>(X, X0, cls_topic, pw, pb, mixer, PV);
    norm_kernel<<<32, 256>>>(PV, out);
    score_kernel<<<16, 256>>>(out);
}